// round 7
// baseline (speedup 1.0000x reference)
#include <cuda_runtime.h>
#include <cuda_bf16.h>
#include <math.h>
#include <stdint.h>

// Problem constants
#define BB 4
#define TT 2048
#define DM 1024
#define HH 16
#define DH 64
#define MM (BB*TT)          // 8192 rows
#define K3 3072             // split-K: [hi | hi | lo] (A)  x  [hi | lo | hi] (W)
#define NWC 6400            // W_cat rows: 5*1024 proj + 16 b + 16 g + 224 pad + 1024 Wo
#define NC 48               // K3 / 64

// ---------------- scratch ----------------
__device__ __nv_bfloat16 g_acat[(size_t)MM*K3];
__device__ __nv_bfloat16 g_ocat[(size_t)MM*K3];
__device__ __nv_bfloat16 g_wcat[(size_t)NWC*K3];
__device__ float g_q   [(size_t)MM*DM];
__device__ float g_k   [(size_t)MM*DM];
__device__ float g_v   [(size_t)MM*DM];
__device__ float g_a   [(size_t)MM*DM];
__device__ float g_ar  [(size_t)MM*DM];
__device__ float g_beta [(size_t)MM*HH];
__device__ float g_gamma[(size_t)MM*HH];

__device__ __forceinline__ float sigmoidf_(float x) {
    return 1.0f / (1.0f + expf(-x));
}
__device__ __forceinline__ uint32_t smem_u32(const void* p) {
    return (uint32_t)__cvta_generic_to_shared(p);
}
__device__ __forceinline__ void cp16(uint32_t s, const void* g) {
    asm volatile("cp.async.cg.shared.global [%0], [%1], 16;" :: "r"(s), "l"(g));
}
#define CP_COMMIT() asm volatile("cp.async.commit_group;")
#define CP_WAIT(n)  asm volatile("cp.async.wait_group %0;" :: "n"(n))

#define LDSM_X4(r, addr) \
    asm volatile("ldmatrix.sync.aligned.m8n8.x4.shared.b16 {%0,%1,%2,%3}, [%4];" \
                 : "=r"((r)[0]), "=r"((r)[1]), "=r"((r)[2]), "=r"((r)[3]) : "r"(addr))

#define MMA16816(c, a, b0_, b1_) \
    asm volatile("mma.sync.aligned.m16n8k16.row.col.f32.bf16.bf16.f32 " \
                 "{%0,%1,%2,%3}, {%4,%5,%6,%7}, {%8,%9}, {%0,%1,%2,%3};" \
                 : "+f"((c)[0]), "+f"((c)[1]), "+f"((c)[2]), "+f"((c)[3]) \
                 : "r"((a)[0]), "r"((a)[1]), "r"((a)[2]), "r"((a)[3]), \
                   "r"(b0_), "r"(b1_))

#define GEMM_SMEM (65536 + 1024)

// ---------------- hi/lo split store helper ----------------
__device__ __forceinline__ void store_split(__nv_bfloat16* dst, size_t base, int c,
                                            float4 v, bool a_layout) {
    __nv_bfloat16 h0 = __float2bfloat16(v.x), h1 = __float2bfloat16(v.y);
    __nv_bfloat16 h2 = __float2bfloat16(v.z), h3 = __float2bfloat16(v.w);
    __nv_bfloat16 l0 = __float2bfloat16(v.x - __bfloat162float(h0));
    __nv_bfloat16 l1 = __float2bfloat16(v.y - __bfloat162float(h1));
    __nv_bfloat16 l2 = __float2bfloat16(v.z - __bfloat162float(h2));
    __nv_bfloat16 l3 = __float2bfloat16(v.w - __bfloat162float(h3));
    __nv_bfloat162 hp0; hp0.x = h0; hp0.y = h1;
    __nv_bfloat162 hp1; hp1.x = h2; hp1.y = h3;
    __nv_bfloat162 lp0; lp0.x = l0; lp0.y = l1;
    __nv_bfloat162 lp1; lp1.x = l2; lp1.y = l3;
    __nv_bfloat162* p0 = (__nv_bfloat162*)(dst + base + c);
    __nv_bfloat162* p1 = (__nv_bfloat162*)(dst + base + 1024 + c);
    __nv_bfloat162* p2 = (__nv_bfloat162*)(dst + base + 2048 + c);
    p0[0] = hp0; p0[1] = hp1;
    if (a_layout) { p1[0] = hp0; p1[1] = hp1; p2[0] = lp0; p2[1] = lp1; }
    else          { p1[0] = lp0; p1[1] = lp1; p2[0] = hp0; p2[1] = hp1; }
}

// ---------------- LayerNorm -> A_cat (bf16 hi/hi/lo) ----------------
__global__ void ln_kernel(const float* __restrict__ x,
                          const float* __restrict__ w,
                          const float* __restrict__ bsh) {
    __shared__ float sh[8];
    const int m = blockIdx.x;
    const int tid = threadIdx.x;
    const float* xr = x + (size_t)m * DM;

    float4 xv = *(const float4*)(xr + tid * 4);
    float s = xv.x + xv.y + xv.z + xv.w;
    #pragma unroll
    for (int o = 16; o; o >>= 1) s += __shfl_xor_sync(0xffffffffu, s, o);
    if ((tid & 31) == 0) sh[tid >> 5] = s;
    __syncthreads();
    float tot = 0.f;
    #pragma unroll
    for (int i = 0; i < 8; i++) tot += sh[i];
    const float mean = tot * (1.0f / 1024.0f);
    __syncthreads();

    float dx0 = xv.x - mean, dx1 = xv.y - mean, dx2 = xv.z - mean, dx3 = xv.w - mean;
    float s2 = dx0*dx0 + dx1*dx1 + dx2*dx2 + dx3*dx3;
    #pragma unroll
    for (int o = 16; o; o >>= 1) s2 += __shfl_xor_sync(0xffffffffu, s2, o);
    if ((tid & 31) == 0) sh[tid >> 5] = s2;
    __syncthreads();
    float tot2 = 0.f;
    #pragma unroll
    for (int i = 0; i < 8; i++) tot2 += sh[i];
    const float rstd = rsqrtf(tot2 * (1.0f / 1024.0f) + 1e-5f);

    float4 wv = *(const float4*)(w + tid * 4);
    float4 bv = *(const float4*)(bsh + tid * 4);
    float4 ov;
    ov.x = dx0 * rstd * wv.x + bv.x;
    ov.y = dx1 * rstd * wv.y + bv.y;
    ov.z = dx2 * rstd * wv.z + bv.z;
    ov.w = dx3 * rstd * wv.w + bv.w;

    store_split(g_acat, (size_t)m * K3, tid * 4, ov, true);
}

// ---------------- W_cat builder ----------------
__global__ void conv_w(const float* __restrict__ Wq, const float* __restrict__ Wk,
                       const float* __restrict__ Wv, const float* __restrict__ Wa,
                       const float* __restrict__ War, const float* __restrict__ Wb,
                       const float* __restrict__ Wg, const float* __restrict__ Wo) {
    const int n = blockIdx.x;
    const int c = threadIdx.x * 4;
    float4 v = {0.f, 0.f, 0.f, 0.f};
    const float* src = nullptr;
    if (n < 5120) {
        const int seg = n >> 10;
        const float* tab[5] = {Wq, Wk, Wv, Wa, War};
        src = tab[seg] + (size_t)(n & 1023) * DM;
    } else if (n < 5136) {
        src = Wb + (size_t)(n - 5120) * DM;
    } else if (n < 5152) {
        src = Wg + (size_t)(n - 5136) * DM;
    } else if (n >= 5376) {
        src = Wo + (size_t)(n - 5376) * DM;
    }
    if (src) v = *(const float4*)(src + c);
    store_split(g_wcat, (size_t)n * K3, c, v, false);
}

// ---------------- epilogue writer (2 consecutive cols) ----------------
__device__ __forceinline__ void epi_write2(int m, int n, float v0, float v1,
        const float* __restrict__ ba, const float* __restrict__ baR,
        const float* __restrict__ bb, const float* __restrict__ bgm,
        const float* __restrict__ xres, float* __restrict__ dout) {
    if (n < 3072) {
        float* outp = (n < 1024) ? g_q : (n < 2048 ? g_k : g_v);
        float2 w; w.x = v0; w.y = v1;
        *(float2*)(outp + (size_t)m * DM + (n & 1023)) = w;
    } else if (n < 5120) {
        float* outp = (n < 4096) ? g_a : g_ar;
        const float* bias = (n < 4096) ? ba : baR;
        const int col = n & 1023;
        float2 w;
        w.x = sigmoidf_(v0 + bias[col]);
        w.y = sigmoidf_(v1 + bias[col + 1]);
        *(float2*)(outp + (size_t)m * DM + col) = w;
    } else if (n < 5136) {
        const int j = n - 5120;
        g_beta[(size_t)m * HH + j]     = sigmoidf_(v0 + bb[j]);
        g_beta[(size_t)m * HH + j + 1] = sigmoidf_(v1 + bb[j + 1]);
    } else if (n < 5152) {
        const int j = n - 5136;
        g_gamma[(size_t)m * HH + j]     = sigmoidf_(v0 + bgm[j]);
        g_gamma[(size_t)m * HH + j + 1] = sigmoidf_(v1 + bgm[j + 1]);
    } else if (n < 5376) {
        // pad: drop
    } else {
        const int col = n - 5376;
        float2 r = *(const float2*)(xres + (size_t)m * DM + col);
        float2 w; w.x = v0 + r.x; w.y = v1 + r.y;
        *(float2*)(dout + (size_t)m * DM + col) = w;
    }
}

// ---- mma.sync bf16 GEMM: 128x128 CTA, 64x32 warp, 2-stage (R3 config) ----
__global__ void __launch_bounds__(256, 2)
gemm_mma(const __nv_bfloat16* __restrict__ A,
         const __nv_bfloat16* __restrict__ Wc,
         int nbase,
         const float* __restrict__ ba, const float* __restrict__ baR,
         const float* __restrict__ bb, const float* __restrict__ bgm,
         const float* __restrict__ xres, float* __restrict__ dout) {
    extern __shared__ __align__(16) char dsm[];
    const int tid = threadIdx.x;
    const int wid = tid >> 5, lane = tid & 31;
    const int m0 = blockIdx.x * 128;
    const int n0g = nbase + blockIdx.y * 128;

    const uint32_t sbase = smem_u32(dsm);
    const uint32_t tile0 = (sbase + 1023) & ~1023u;
    const uint32_t sA = tile0;
    const uint32_t sW = tile0 + 32768;

    const __nv_bfloat16* Aptr = A + (size_t)m0 * K3;
    const __nv_bfloat16* Wptr = Wc + (size_t)n0g * K3;

    int cp_r[4], cp_soff[4];
    #pragma unroll
    for (int i = 0; i < 4; i++) {
        const int u = tid + i * 256;
        const int r = u >> 3, c16 = u & 7;
        cp_r[i] = r;
        cp_soff[i] = r * 128 + ((c16 ^ (r & 7)) * 16);
    }

#define ISSUE(cc_) do { \
    const int kc_ = (cc_) * 64; \
    const uint32_t ab_ = sA + ((cc_) & 1) * 16384; \
    const uint32_t wb_ = sW + ((cc_) & 1) * 16384; \
    _Pragma("unroll") \
    for (int i_ = 0; i_ < 4; i_++) { \
        const int c16_ = (tid + i_ * 256) & 7; \
        cp16(ab_ + cp_soff[i_], Aptr + (size_t)cp_r[i_] * K3 + kc_ + c16_ * 8); \
        cp16(wb_ + cp_soff[i_], Wptr + (size_t)cp_r[i_] * K3 + kc_ + c16_ * 8); \
    } \
    CP_COMMIT(); \
} while (0)

    float acc[4][4][4];
    #pragma unroll
    for (int i = 0; i < 4; i++)
        #pragma unroll
        for (int j = 0; j < 4; j++)
            #pragma unroll
            for (int e = 0; e < 4; e++) acc[i][j][e] = 0.f;

    const int mwarp = (wid >> 2) * 64;
    const int nwarp = (wid & 3) * 32;
    const int lrow  = lane & 15;
    const int lchunk = lane >> 4;

    ISSUE(0);
    ISSUE(1);

    for (int c = 0; c < NC; c++) {
        if (c + 1 < NC) { CP_WAIT(1); } else { CP_WAIT(0); }
        __syncthreads();

        const uint32_t ab = sA + (c & 1) * 16384;
        const uint32_t wb = sW + (c & 1) * 16384;

        #pragma unroll
        for (int ks = 0; ks < 4; ks++) {
            const int cc = ks * 2 + lchunk;
            uint32_t ar[4][4];
            #pragma unroll
            for (int fm = 0; fm < 4; fm++) {
                const int rr = mwarp + fm * 16 + lrow;
                LDSM_X4(ar[fm], ab + rr * 128 + ((cc ^ (rr & 7)) * 16));
            }
            uint32_t br[2][4];
            #pragma unroll
            for (int g = 0; g < 2; g++) {
                const int rr = nwarp + g * 16 + lrow;
                LDSM_X4(br[g], wb + rr * 128 + ((cc ^ (rr & 7)) * 16));
            }
            #pragma unroll
            for (int fm = 0; fm < 4; fm++)
                #pragma unroll
                for (int fn = 0; fn < 4; fn++)
                    MMA16816(acc[fm][fn], ar[fm],
                             br[fn >> 1][fn & 1], br[fn >> 1][2 + (fn & 1)]);
        }

        __syncthreads();
        if (c + 2 < NC) ISSUE(c + 2);
    }
#undef ISSUE

    // ---- epilogue ----
    const int mrow_lo = m0 + mwarp + (lane >> 2);
    const int ncol = n0g + nwarp + (lane & 3) * 2;
    #pragma unroll
    for (int fm = 0; fm < 4; fm++) {
        const int m_lo = mrow_lo + fm * 16;
        #pragma unroll
        for (int fn = 0; fn < 4; fn++) {
            const int n = ncol + fn * 8;
            epi_write2(m_lo,     n, acc[fm][fn][0], acc[fm][fn][1], ba, baR, bb, bgm, xres, dout);
            epi_write2(m_lo + 8, n, acc[fm][fn][2], acc[fm][fn][3], ba, baR, bb, bgm, xres, dout);
        }
    }
}

// ---------------- sequential scan: 64 blocks x 512 threads ----------------
// One block per (b,h). Single __syncthreads per step; staging of step t+1
// overlaps compute of step t; 2-step-deep gmem prefetch via parity registers.

#define SCAN_STAGE(pp_, f_) do { \
    if (g == 0) { \
        sk[pp_][idx] = (f_); \
        float nn_ = (f_) * (f_); \
        _Pragma("unroll") \
        for (int o_ = 16; o_; o_ >>= 1) nn_ += __shfl_xor_sync(0xffffffffu, nn_, o_); \
        if ((tid & 31) == 0) snrm[pp_][(tid >> 5) & 1] = nn_; \
    } else if (g == 1) { sq[pp_][idx] = (f_); } \
    else if (g == 2) { sv[pp_][idx] = (f_); } \
    else if (g == 3) { sa[pp_][idx] = (f_); } \
    else if (g == 4) { sr[pp_][idx] = (f_); } \
    else if (g == 5 && idx < 2) { sbg[pp_][idx] = (f_); } \
} while (0)

__global__ void __launch_bounds__(512, 1)
scan_kernel(const float* __restrict__ Q, const float* __restrict__ K,
            const float* __restrict__ V, const float* __restrict__ A,
            const float* __restrict__ AR,
            const float* __restrict__ Bt, const float* __restrict__ Gt,
            __nv_bfloat16* __restrict__ Ocat) {
    const int bh = blockIdx.x;           // 0..63
    const int b = bh >> 4, h = bh & 15;
    const int tid = threadIdx.x;
    const int e  = tid >> 3;             // column 0..63
    const int r8 = tid & 7;              // row octet

    const size_t rb  = ((size_t)b * TT) * DM + (size_t)h * DH;
    size_t ob        = ((size_t)b * TT) * K3 + (size_t)h * DH + e;
    const size_t bgb = ((size_t)b * TT) * HH + h;

    __shared__ __align__(16) float sk[2][64], sq[2][64], sv[2][64], sa[2][64], sr[2][64];
    __shared__ float snrm[2][2], sbg[2][2];

    float S[8], R[8];
    #pragma unroll
    for (int i = 0; i < 8; i++) { S[i] = 0.f; R[i] = 0.f; }

    // staging role: 8 groups of 64 threads
    const int g = tid >> 6, idx = tid & 63;
    const float* p0 = nullptr; int s0 = 0;
    if      (g == 0) { p0 = K  + rb + idx; s0 = DM; }
    else if (g == 1) { p0 = Q  + rb + idx; s0 = DM; }
    else if (g == 2) { p0 = V  + rb + idx; s0 = DM; }
    else if (g == 3) { p0 = A  + rb + idx; s0 = DM; }
    else if (g == 4) { p0 = AR + rb + idx; s0 = DM; }
    else if (g == 5 && idx == 0) { p0 = Bt + bgb; s0 = HH; }
    else if (g == 5 && idx == 1) { p0 = Gt + bgb; s0 = HH; }

    // prologue: stage step 0; prefetch steps 1 (fA) and 2 (fB)
    float fA = 0.f, fB = 0.f;
    if (p0) {
        float f0 = __ldg(p0);
        SCAN_STAGE(0, f0);
        p0 += s0; fA = __ldg(p0);
        p0 += s0; fB = __ldg(p0);
    } else {
        SCAN_STAGE(0, 0.f);   // no-op for groups without a pointer
    }

    for (int t = 0; t < TT; t++) {
        const int p = t & 1;
        __syncthreads();   // smem[p] staged; protects smem[p^1] writes below

        // ---- stage step t+1, prefetch step t+3 (2-iteration latency window) ----
        if (t + 1 < TT) {
            if (t & 1) {
                SCAN_STAGE(p ^ 1, fB);
                if (p0 && t + 3 < TT) { p0 += s0; fB = __ldg(p0); }
            } else {
                SCAN_STAGE(p ^ 1, fA);
                if (p0 && t + 3 < TT) { p0 += s0; fA = __ldg(p0); }
            }
        }

        // ---- compute step t ----
        const float nrm2 = snrm[p][0] + snrm[p][1];
        const float invn = rsqrtf(fmaxf(nrm2, 1e-24f));

        float4 k0 = *(const float4*)&sk[p][r8 * 8];
        float4 k1 = *(const float4*)&sk[p][r8 * 8 + 4];
        float kn[8] = {k0.x*invn, k0.y*invn, k0.z*invn, k0.w*invn,
                       k1.x*invn, k1.y*invn, k1.z*invn, k1.w*invn};
        float4 q0 = *(const float4*)&sq[p][r8 * 8];
        float4 q1 = *(const float4*)&sq[p][r8 * 8 + 4];
        float qv[8] = {q0.x, q0.y, q0.z, q0.w, q1.x, q1.y, q1.z, q1.w};

        const float beta  = sbg[p][0];
        const float gamma = sbg[p][1];
        const float ve = sv[p][e];

        // pred = S^T kn (uses pre-decay S)
        float pr = 0.f;
        #pragma unroll
        for (int i = 0; i < 8; i++) pr = fmaf(S[i], kn[i], pr);
        pr += __shfl_xor_sync(0xffffffffu, pr, 1);
        pr += __shfl_xor_sync(0xffffffffu, pr, 2);
        pr += __shfl_xor_sync(0xffffffffu, pr, 4);
        const float re = fminf(fmaxf(ve - pr, -1.0f), 1.0f);

        // S: decay, kp, rank-1 update, oS
        float4 a0 = *(const float4*)&sa[p][r8 * 8];
        float4 a1 = *(const float4*)&sa[p][r8 * 8 + 4];
        float av[8] = {a0.x, a0.y, a0.z, a0.w, a1.x, a1.y, a1.z, a1.w};
        float kp = 0.f;
        #pragma unroll
        for (int i = 0; i < 8; i++) { S[i] *= av[i]; kp = fmaf(kn[i], S[i], kp); }
        kp += __shfl_xor_sync(0xffffffffu, kp, 1);
        kp += __shfl_xor_sync(0xffffffffu, kp, 2);
        kp += __shfl_xor_sync(0xffffffffu, kp, 4);
        const float cf = beta * (ve - kp);
        float os = 0.f;
        #pragma unroll
        for (int i = 0; i < 8; i++) { S[i] = fmaf(kn[i], cf, S[i]); os = fmaf(S[i], qv[i], os); }

        // R: decay, kr, rank-1 update with target re, oR
        float4 r0 = *(const float4*)&sr[p][r8 * 8];
        float4 r1 = *(const float4*)&sr[p][r8 * 8 + 4];
        float rv[8] = {r0.x, r0.y, r0.z, r0.w, r1.x, r1.y, r1.z, r1.w};
        float kr = 0.f;
        #pragma unroll
        for (int i = 0; i < 8; i++) { R[i] *= rv[i]; kr = fmaf(kn[i], R[i], kr); }
        kr += __shfl_xor_sync(0xffffffffu, kr, 1);
        kr += __shfl_xor_sync(0xffffffffu, kr, 2);
        kr += __shfl_xor_sync(0xffffffffu, kr, 4);
        const float cr = gamma * (re - kr);
        #pragma unroll
        for (int i = 0; i < 8; i++) { R[i] = fmaf(kn[i], cr, R[i]); os = fmaf(R[i], qv[i], os); }

        os += __shfl_xor_sync(0xffffffffu, os, 1);
        os += __shfl_xor_sync(0xffffffffu, os, 2);
        os += __shfl_xor_sync(0xffffffffu, os, 4);

        if (r8 == 0) {
            __nv_bfloat16 hv = __float2bfloat16(os);
            __nv_bfloat16 lv = __float2bfloat16(os - __bfloat162float(hv));
            Ocat[ob]        = hv;
            Ocat[ob + 1024] = hv;
            Ocat[ob + 2048] = lv;
        }
        ob += K3;
    }
}

// ---------------- launch ----------------
extern "C" void kernel_launch(void* const* d_in, const int* in_sizes, int n_in,
                              void* d_out, int out_size) {
    const float* x    = (const float*)d_in[0];
    const float* Wq   = (const float*)d_in[1];
    const float* Wk   = (const float*)d_in[2];
    const float* Wv   = (const float*)d_in[3];
    const float* Wa   = (const float*)d_in[4];
    const float* ba   = (const float*)d_in[5];
    const float* Wb   = (const float*)d_in[6];
    const float* bb   = (const float*)d_in[7];
    const float* Wg   = (const float*)d_in[8];
    const float* bgm  = (const float*)d_in[9];
    const float* War  = (const float*)d_in[10];
    const float* baR  = (const float*)d_in[11];
    const float* Wo   = (const float*)d_in[12];
    const float* ln_w = (const float*)d_in[13];
    const float* ln_b = (const float*)d_in[14];
    float* out = (float*)d_out;

    __nv_bfloat16 *acat, *ocat, *wcat;
    float *q, *k, *v, *a, *ar, *bet, *gam;
    cudaGetSymbolAddress((void**)&acat, g_acat);
    cudaGetSymbolAddress((void**)&ocat, g_ocat);
    cudaGetSymbolAddress((void**)&wcat, g_wcat);
    cudaGetSymbolAddress((void**)&q,   g_q);
    cudaGetSymbolAddress((void**)&k,   g_k);
    cudaGetSymbolAddress((void**)&v,   g_v);
    cudaGetSymbolAddress((void**)&a,   g_a);
    cudaGetSymbolAddress((void**)&ar,  g_ar);
    cudaGetSymbolAddress((void**)&bet, g_beta);
    cudaGetSymbolAddress((void**)&gam, g_gamma);

    static int smem_set = 0;
    if (!smem_set) {
        cudaFuncSetAttribute(gemm_mma, cudaFuncAttributeMaxDynamicSharedMemorySize, GEMM_SMEM);
        smem_set = 1;
    }

    ln_kernel<<<MM, 256>>>(x, ln_w, ln_b);
    conv_w<<<NWC, 256>>>(Wq, Wk, Wv, Wa, War, Wb, Wg, Wo);
    // proj + head gates: n in [0, 5376)
    gemm_mma<<<dim3(MM/128, 42), 256, GEMM_SMEM>>>(acat, wcat, 0, ba, baR, bb, bgm,
                                                   nullptr, nullptr);
    scan_kernel<<<64, 512>>>(q, k, v, a, ar, bet, gam, ocat);
    // output proj: n in [5376, 6400)
    gemm_mma<<<dim3(MM/128, 8), 256, GEMM_SMEM>>>(ocat, wcat, 5376, ba, baR, bb, bgm,
                                                  x, out);
}

// round 8
// speedup vs baseline: 1.3881x; 1.3881x over previous
#include <cuda_runtime.h>
#include <cuda_fp16.h>
#include <math.h>
#include <stdint.h>

// Problem constants
#define BB 4
#define TT 2048
#define DM 1024
#define HH 16
#define DH 64
#define MM (BB*TT)          // 8192 rows
#define K2 2048             // split-K: [Ah | Al] (A)  x  [Wh | Wh] (W)  => A . fp16(W)
#define NWC 6400            // W_cat rows: 5*1024 proj + 16 b + 16 g + 224 pad + 1024 Wo
#define NC 32               // K2 / 64

// ---------------- scratch ----------------
__device__ __half g_acat[(size_t)MM*K2];
__device__ __half g_ocat[(size_t)MM*K2];
__device__ __half g_wcat[(size_t)NWC*K2];
__device__ float g_q   [(size_t)MM*DM];
__device__ float g_k   [(size_t)MM*DM];
__device__ float g_v   [(size_t)MM*DM];
__device__ float g_a   [(size_t)MM*DM];
__device__ float g_ar  [(size_t)MM*DM];
__device__ float g_beta [(size_t)MM*HH];
__device__ float g_gamma[(size_t)MM*HH];

__device__ __forceinline__ float sigmoidf_(float x) {
    return 1.0f / (1.0f + expf(-x));
}
__device__ __forceinline__ uint32_t smem_u32(const void* p) {
    return (uint32_t)__cvta_generic_to_shared(p);
}
__device__ __forceinline__ void cp16(uint32_t s, const void* g) {
    asm volatile("cp.async.cg.shared.global [%0], [%1], 16;" :: "r"(s), "l"(g));
}
#define CP_COMMIT() asm volatile("cp.async.commit_group;")
#define CP_WAIT(n)  asm volatile("cp.async.wait_group %0;" :: "n"(n))

#define LDSM_X4(r, addr) \
    asm volatile("ldmatrix.sync.aligned.m8n8.x4.shared.b16 {%0,%1,%2,%3}, [%4];" \
                 : "=r"((r)[0]), "=r"((r)[1]), "=r"((r)[2]), "=r"((r)[3]) : "r"(addr))

#define MMA16816(c, a, b0_, b1_) \
    asm volatile("mma.sync.aligned.m16n8k16.row.col.f32.f16.f16.f32 " \
                 "{%0,%1,%2,%3}, {%4,%5,%6,%7}, {%8,%9}, {%0,%1,%2,%3};" \
                 : "+f"((c)[0]), "+f"((c)[1]), "+f"((c)[2]), "+f"((c)[3]) \
                 : "r"((a)[0]), "r"((a)[1]), "r"((a)[2]), "r"((a)[3]), \
                   "r"(b0_), "r"(b1_))

#define GEMM_SMEM (65536 + 1024)

// ---------------- hi/lo fp16 split store (2 segments) ----------------
// a_layout=true:  [hi @ 0, lo @ 1024]   (A side: exact 2-term representation)
// a_layout=false: [hi @ 0, hi @ 1024]   (W side: duplicated fp16 weights)
__device__ __forceinline__ void store_split(__half* dst, size_t base, int c,
                                            float4 v, bool a_layout) {
    __half h0 = __float2half_rn(v.x), h1 = __float2half_rn(v.y);
    __half h2 = __float2half_rn(v.z), h3 = __float2half_rn(v.w);
    __half2 hp0; hp0.x = h0; hp0.y = h1;
    __half2 hp1; hp1.x = h2; hp1.y = h3;
    __half2* p0 = (__half2*)(dst + base + c);
    __half2* p1 = (__half2*)(dst + base + 1024 + c);
    p0[0] = hp0; p0[1] = hp1;
    if (a_layout) {
        __half l0 = __float2half_rn(v.x - __half2float(h0));
        __half l1 = __float2half_rn(v.y - __half2float(h1));
        __half l2 = __float2half_rn(v.z - __half2float(h2));
        __half l3 = __float2half_rn(v.w - __half2float(h3));
        __half2 lp0; lp0.x = l0; lp0.y = l1;
        __half2 lp1; lp1.x = l2; lp1.y = l3;
        p1[0] = lp0; p1[1] = lp1;
    } else {
        p1[0] = hp0; p1[1] = hp1;
    }
}

// ---------------- LayerNorm -> A_cat (fp16 hi/lo) ----------------
__global__ void ln_kernel(const float* __restrict__ x,
                          const float* __restrict__ w,
                          const float* __restrict__ bsh) {
    __shared__ float sh[8];
    const int m = blockIdx.x;
    const int tid = threadIdx.x;
    const float* xr = x + (size_t)m * DM;

    float4 xv = *(const float4*)(xr + tid * 4);
    float s = xv.x + xv.y + xv.z + xv.w;
    #pragma unroll
    for (int o = 16; o; o >>= 1) s += __shfl_xor_sync(0xffffffffu, s, o);
    if ((tid & 31) == 0) sh[tid >> 5] = s;
    __syncthreads();
    float tot = 0.f;
    #pragma unroll
    for (int i = 0; i < 8; i++) tot += sh[i];
    const float mean = tot * (1.0f / 1024.0f);
    __syncthreads();

    float dx0 = xv.x - mean, dx1 = xv.y - mean, dx2 = xv.z - mean, dx3 = xv.w - mean;
    float s2 = dx0*dx0 + dx1*dx1 + dx2*dx2 + dx3*dx3;
    #pragma unroll
    for (int o = 16; o; o >>= 1) s2 += __shfl_xor_sync(0xffffffffu, s2, o);
    if ((tid & 31) == 0) sh[tid >> 5] = s2;
    __syncthreads();
    float tot2 = 0.f;
    #pragma unroll
    for (int i = 0; i < 8; i++) tot2 += sh[i];
    const float rstd = rsqrtf(tot2 * (1.0f / 1024.0f) + 1e-5f);

    float4 wv = *(const float4*)(w + tid * 4);
    float4 bv = *(const float4*)(bsh + tid * 4);
    float4 ov;
    ov.x = dx0 * rstd * wv.x + bv.x;
    ov.y = dx1 * rstd * wv.y + bv.y;
    ov.z = dx2 * rstd * wv.z + bv.z;
    ov.w = dx3 * rstd * wv.w + bv.w;

    store_split(g_acat, (size_t)m * K2, tid * 4, ov, true);
}

// ---------------- W_cat builder ----------------
__global__ void conv_w(const float* __restrict__ Wq, const float* __restrict__ Wk,
                       const float* __restrict__ Wv, const float* __restrict__ Wa,
                       const float* __restrict__ War, const float* __restrict__ Wb,
                       const float* __restrict__ Wg, const float* __restrict__ Wo) {
    const int n = blockIdx.x;
    const int c = threadIdx.x * 4;
    float4 v = {0.f, 0.f, 0.f, 0.f};
    const float* src = nullptr;
    if (n < 5120) {
        const int seg = n >> 10;
        const float* tab[5] = {Wq, Wk, Wv, Wa, War};
        src = tab[seg] + (size_t)(n & 1023) * DM;
    } else if (n < 5136) {
        src = Wb + (size_t)(n - 5120) * DM;
    } else if (n < 5152) {
        src = Wg + (size_t)(n - 5136) * DM;
    } else if (n >= 5376) {
        src = Wo + (size_t)(n - 5376) * DM;
    }
    if (src) v = *(const float4*)(src + c);
    store_split(g_wcat, (size_t)n * K2, c, v, false);
}

// ---------------- epilogue writer (2 consecutive cols) ----------------
__device__ __forceinline__ void epi_write2(int m, int n, float v0, float v1,
        const float* __restrict__ ba, const float* __restrict__ baR,
        const float* __restrict__ bb, const float* __restrict__ bgm,
        const float* __restrict__ xres, float* __restrict__ dout) {
    if (n < 3072) {
        float* outp = (n < 1024) ? g_q : (n < 2048 ? g_k : g_v);
        float2 w; w.x = v0; w.y = v1;
        *(float2*)(outp + (size_t)m * DM + (n & 1023)) = w;
    } else if (n < 5120) {
        float* outp = (n < 4096) ? g_a : g_ar;
        const float* bias = (n < 4096) ? ba : baR;
        const int col = n & 1023;
        float2 w;
        w.x = sigmoidf_(v0 + bias[col]);
        w.y = sigmoidf_(v1 + bias[col + 1]);
        *(float2*)(outp + (size_t)m * DM + col) = w;
    } else if (n < 5136) {
        const int j = n - 5120;
        g_beta[(size_t)m * HH + j]     = sigmoidf_(v0 + bb[j]);
        g_beta[(size_t)m * HH + j + 1] = sigmoidf_(v1 + bb[j + 1]);
    } else if (n < 5152) {
        const int j = n - 5136;
        g_gamma[(size_t)m * HH + j]     = sigmoidf_(v0 + bgm[j]);
        g_gamma[(size_t)m * HH + j + 1] = sigmoidf_(v1 + bgm[j + 1]);
    } else if (n < 5376) {
        // pad: drop
    } else {
        const int col = n - 5376;
        float2 r = *(const float2*)(xres + (size_t)m * DM + col);
        float2 w; w.x = v0 + r.x; w.y = v1 + r.y;
        *(float2*)(dout + (size_t)m * DM + col) = w;
    }
}

// ---- mma.sync fp16 GEMM: 128x128 CTA, 64x32 warp, 2-stage (R3 config) ----
__global__ void __launch_bounds__(256, 2)
gemm_mma(const __half* __restrict__ A,
         const __half* __restrict__ Wc,
         int nbase,
         const float* __restrict__ ba, const float* __restrict__ baR,
         const float* __restrict__ bb, const float* __restrict__ bgm,
         const float* __restrict__ xres, float* __restrict__ dout) {
    extern __shared__ __align__(16) char dsm[];
    const int tid = threadIdx.x;
    const int wid = tid >> 5, lane = tid & 31;
    const int m0 = blockIdx.x * 128;
    const int n0g = nbase + blockIdx.y * 128;

    const uint32_t sbase = smem_u32(dsm);
    const uint32_t tile0 = (sbase + 1023) & ~1023u;
    const uint32_t sA = tile0;
    const uint32_t sW = tile0 + 32768;

    const __half* Aptr = A + (size_t)m0 * K2;
    const __half* Wptr = Wc + (size_t)n0g * K2;

    int cp_r[4], cp_soff[4];
    #pragma unroll
    for (int i = 0; i < 4; i++) {
        const int u = tid + i * 256;
        const int r = u >> 3, c16 = u & 7;
        cp_r[i] = r;
        cp_soff[i] = r * 128 + ((c16 ^ (r & 7)) * 16);
    }

#define ISSUE(cc_) do { \
    const int kc_ = (cc_) * 64; \
    const uint32_t ab_ = sA + ((cc_) & 1) * 16384; \
    const uint32_t wb_ = sW + ((cc_) & 1) * 16384; \
    _Pragma("unroll") \
    for (int i_ = 0; i_ < 4; i_++) { \
        const int c16_ = (tid + i_ * 256) & 7; \
        cp16(ab_ + cp_soff[i_], Aptr + (size_t)cp_r[i_] * K2 + kc_ + c16_ * 8); \
        cp16(wb_ + cp_soff[i_], Wptr + (size_t)cp_r[i_] * K2 + kc_ + c16_ * 8); \
    } \
    CP_COMMIT(); \
} while (0)

    float acc[4][4][4];
    #pragma unroll
    for (int i = 0; i < 4; i++)
        #pragma unroll
        for (int j = 0; j < 4; j++)
            #pragma unroll
            for (int e = 0; e < 4; e++) acc[i][j][e] = 0.f;

    const int mwarp = (wid >> 2) * 64;
    const int nwarp = (wid & 3) * 32;
    const int lrow  = lane & 15;
    const int lchunk = lane >> 4;

    ISSUE(0);
    ISSUE(1);

    for (int c = 0; c < NC; c++) {
        if (c + 1 < NC) { CP_WAIT(1); } else { CP_WAIT(0); }
        __syncthreads();

        const uint32_t ab = sA + (c & 1) * 16384;
        const uint32_t wb = sW + (c & 1) * 16384;

        #pragma unroll
        for (int ks = 0; ks < 4; ks++) {
            const int cc = ks * 2 + lchunk;
            uint32_t ar[4][4];
            #pragma unroll
            for (int fm = 0; fm < 4; fm++) {
                const int rr = mwarp + fm * 16 + lrow;
                LDSM_X4(ar[fm], ab + rr * 128 + ((cc ^ (rr & 7)) * 16));
            }
            uint32_t br[2][4];
            #pragma unroll
            for (int g = 0; g < 2; g++) {
                const int rr = nwarp + g * 16 + lrow;
                LDSM_X4(br[g], wb + rr * 128 + ((cc ^ (rr & 7)) * 16));
            }
            #pragma unroll
            for (int fm = 0; fm < 4; fm++)
                #pragma unroll
                for (int fn = 0; fn < 4; fn++)
                    MMA16816(acc[fm][fn], ar[fm],
                             br[fn >> 1][fn & 1], br[fn >> 1][2 + (fn & 1)]);
        }

        __syncthreads();
        if (c + 2 < NC) ISSUE(c + 2);
    }
#undef ISSUE

    // ---- epilogue ----
    const int mrow_lo = m0 + mwarp + (lane >> 2);
    const int ncol = n0g + nwarp + (lane & 3) * 2;
    #pragma unroll
    for (int fm = 0; fm < 4; fm++) {
        const int m_lo = mrow_lo + fm * 16;
        #pragma unroll
        for (int fn = 0; fn < 4; fn++) {
            const int n = ncol + fn * 8;
            epi_write2(m_lo,     n, acc[fm][fn][0], acc[fm][fn][1], ba, baR, bb, bgm, xres, dout);
            epi_write2(m_lo + 8, n, acc[fm][fn][2], acc[fm][fn][3], ba, baR, bb, bgm, xres, dout);
        }
    }
}

// ---------------- sequential scan (R3/R5 proven shape: 128 x 256) ----------------
// Writes O_cat (fp16 hi/lo) directly.
__global__ void __launch_bounds__(256, 1)
scan_kernel(const float* __restrict__ Q, const float* __restrict__ K,
            const float* __restrict__ V, const float* __restrict__ A,
            const float* __restrict__ AR,
            const float* __restrict__ Bt, const float* __restrict__ Gt,
            __half* __restrict__ Ocat) {
    const int bh = blockIdx.x >> 1;
    const int half_ = blockIdx.x & 1;
    const int b = bh >> 4, h = bh & 15;
    const int tid = threadIdx.x;
    const int c = tid >> 3;
    const int r8 = tid & 7;
    const int e = half_ * 32 + c;

    size_t rb  = ((size_t)b * TT) * DM + (size_t)h * DH;
    size_t ob  = ((size_t)b * TT) * K2 + (size_t)h * DH + e;
    const size_t bgb = ((size_t)b * TT) * HH + h;

    __shared__ __align__(16) float sk[2][64], sq[2][64], sv[2][64], sa[2][64], sr[2][64];
    __shared__ float snrm[2][2], sbg[2][2];

    float S[8], R[8];
    #pragma unroll
    for (int i = 0; i < 8; i++) { S[i] = 0.f; R[i] = 0.f; }

    const int g = tid >> 6, idx = tid & 63;
    const float* p0 = nullptr; const float* p1 = nullptr;
    int s0 = DM, s1 = 0;
    if (g == 0)      { p0 = K + rb + idx; p1 = Q + rb + idx; s1 = DM; }
    else if (g == 1) { p0 = V + rb + idx;
                       if (idx == 0)      { p1 = Bt + bgb; s1 = HH; }
                       else if (idx == 1) { p1 = Gt + bgb; s1 = HH; } }
    else if (g == 2) { p0 = A + rb + idx; }
    else             { p0 = AR + rb + idx; }

    float f0 = *p0;
    float f1 = (s1 ? *p1 : 0.f);

    for (int t = 0; t < TT; t++) {
        const int p = t & 1;
        if (g == 0) {
            sk[p][idx] = f0; sq[p][idx] = f1;
            float nn = f0 * f0;
            #pragma unroll
            for (int o = 16; o; o >>= 1) nn += __shfl_xor_sync(0xffffffffu, nn, o);
            if ((tid & 31) == 0) snrm[p][tid >> 5] = nn;
        } else if (g == 1) {
            sv[p][idx] = f0;
            if (idx < 2) sbg[p][idx] = f1;
        } else if (g == 2) {
            sa[p][idx] = f0;
        } else {
            sr[p][idx] = f0;
        }
        __syncthreads();

        if (t + 1 < TT) {
            p0 += s0; f0 = __ldg(p0);
            if (s1) { p1 += s1; f1 = __ldg(p1); }
        }

        const float nrm2 = snrm[p][0] + snrm[p][1];
        const float invn = 1.0f / fmaxf(sqrtf(nrm2), 1e-12f);

        float4 k0 = *(const float4*)&sk[p][r8 * 8];
        float4 k1 = *(const float4*)&sk[p][r8 * 8 + 4];
        float kn[8] = {k0.x*invn, k0.y*invn, k0.z*invn, k0.w*invn,
                       k1.x*invn, k1.y*invn, k1.z*invn, k1.w*invn};
        float4 q0 = *(const float4*)&sq[p][r8 * 8];
        float4 q1 = *(const float4*)&sq[p][r8 * 8 + 4];
        float qv[8] = {q0.x, q0.y, q0.z, q0.w, q1.x, q1.y, q1.z, q1.w};

        const float beta  = sbg[p][0];
        const float gamma = sbg[p][1];
        const float ve = sv[p][e];

        float pr = 0.f;
        #pragma unroll
        for (int i = 0; i < 8; i++) pr = fmaf(S[i], kn[i], pr);
        pr += __shfl_xor_sync(0xffffffffu, pr, 1);
        pr += __shfl_xor_sync(0xffffffffu, pr, 2);
        pr += __shfl_xor_sync(0xffffffffu, pr, 4);
        const float re = fminf(fmaxf(ve - pr, -1.0f), 1.0f);

        float4 a0 = *(const float4*)&sa[p][r8 * 8];
        float4 a1 = *(const float4*)&sa[p][r8 * 8 + 4];
        float av[8] = {a0.x, a0.y, a0.z, a0.w, a1.x, a1.y, a1.z, a1.w};
        float kp = 0.f;
        #pragma unroll
        for (int i = 0; i < 8; i++) { S[i] *= av[i]; kp = fmaf(kn[i], S[i], kp); }
        kp += __shfl_xor_sync(0xffffffffu, kp, 1);
        kp += __shfl_xor_sync(0xffffffffu, kp, 2);
        kp += __shfl_xor_sync(0xffffffffu, kp, 4);
        const float cf = beta * (ve - kp);
        float os = 0.f;
        #pragma unroll
        for (int i = 0; i < 8; i++) { S[i] = fmaf(kn[i], cf, S[i]); os = fmaf(S[i], qv[i], os); }

        float4 r0 = *(const float4*)&sr[p][r8 * 8];
        float4 r1 = *(const float4*)&sr[p][r8 * 8 + 4];
        float rv[8] = {r0.x, r0.y, r0.z, r0.w, r1.x, r1.y, r1.z, r1.w};
        float kr = 0.f;
        #pragma unroll
        for (int i = 0; i < 8; i++) { R[i] *= rv[i]; kr = fmaf(kn[i], R[i], kr); }
        kr += __shfl_xor_sync(0xffffffffu, kr, 1);
        kr += __shfl_xor_sync(0xffffffffu, kr, 2);
        kr += __shfl_xor_sync(0xffffffffu, kr, 4);
        const float cr = gamma * (re - kr);
        #pragma unroll
        for (int i = 0; i < 8; i++) { R[i] = fmaf(kn[i], cr, R[i]); os = fmaf(R[i], qv[i], os); }

        os += __shfl_xor_sync(0xffffffffu, os, 1);
        os += __shfl_xor_sync(0xffffffffu, os, 2);
        os += __shfl_xor_sync(0xffffffffu, os, 4);

        if (r8 == 0) {
            __half hv = __float2half_rn(os);
            __half lv = __float2half_rn(os - __half2float(hv));
            Ocat[ob]        = hv;
            Ocat[ob + 1024] = lv;
        }
        rb += DM;
        ob += K2;
    }
}

// ---------------- launch ----------------
extern "C" void kernel_launch(void* const* d_in, const int* in_sizes, int n_in,
                              void* d_out, int out_size) {
    const float* x    = (const float*)d_in[0];
    const float* Wq   = (const float*)d_in[1];
    const float* Wk   = (const float*)d_in[2];
    const float* Wv   = (const float*)d_in[3];
    const float* Wa   = (const float*)d_in[4];
    const float* ba   = (const float*)d_in[5];
    const float* Wb   = (const float*)d_in[6];
    const float* bb   = (const float*)d_in[7];
    const float* Wg   = (const float*)d_in[8];
    const float* bgm  = (const float*)d_in[9];
    const float* War  = (const float*)d_in[10];
    const float* baR  = (const float*)d_in[11];
    const float* Wo   = (const float*)d_in[12];
    const float* ln_w = (const float*)d_in[13];
    const float* ln_b = (const float*)d_in[14];
    float* out = (float*)d_out;

    __half *acat, *ocat, *wcat;
    float *q, *k, *v, *a, *ar, *bet, *gam;
    cudaGetSymbolAddress((void**)&acat, g_acat);
    cudaGetSymbolAddress((void**)&ocat, g_ocat);
    cudaGetSymbolAddress((void**)&wcat, g_wcat);
    cudaGetSymbolAddress((void**)&q,   g_q);
    cudaGetSymbolAddress((void**)&k,   g_k);
    cudaGetSymbolAddress((void**)&v,   g_v);
    cudaGetSymbolAddress((void**)&a,   g_a);
    cudaGetSymbolAddress((void**)&ar,  g_ar);
    cudaGetSymbolAddress((void**)&bet, g_beta);
    cudaGetSymbolAddress((void**)&gam, g_gamma);

    static int smem_set = 0;
    if (!smem_set) {
        cudaFuncSetAttribute(gemm_mma, cudaFuncAttributeMaxDynamicSharedMemorySize, GEMM_SMEM);
        smem_set = 1;
    }

    ln_kernel<<<MM, 256>>>(x, ln_w, ln_b);
    conv_w<<<NWC, 256>>>(Wq, Wk, Wv, Wa, War, Wb, Wg, Wo);
    // proj + head gates: n in [0, 5376)
    gemm_mma<<<dim3(MM/128, 42), 256, GEMM_SMEM>>>(acat, wcat, 0, ba, baR, bb, bgm,
                                                   nullptr, nullptr);
    scan_kernel<<<128, 256>>>(q, k, v, a, ar, bet, gam, ocat);
    // output proj: n in [5376, 6400)
    gemm_mma<<<dim3(MM/128, 8), 256, GEMM_SMEM>>>(ocat, wcat, 5376, ba, baR, bb, bgm,
                                                  x, out);
}

// round 9
// speedup vs baseline: 1.3985x; 1.0075x over previous
#include <cuda_runtime.h>
#include <cuda_fp16.h>
#include <math.h>
#include <stdint.h>

// Problem constants
#define BB 4
#define TT 2048
#define DM 1024
#define HH 16
#define DH 64
#define MM (BB*TT)          // 8192 rows
#define K2 2048             // split-K: [Ah | Al] (A)  x  [Wh | Wh] (W)  => A . fp16(W)
#define NWC 6400            // W_cat rows: 5*1024 proj + 16 b + 16 g + 224 pad + 1024 Wo
#define NC 32               // K2 / 64

// ---------------- scratch ----------------
__device__ __half g_acat[(size_t)MM*K2];
__device__ __half g_ocat[(size_t)MM*K2];
__device__ __half g_wcat[(size_t)NWC*K2];
__device__ float g_q   [(size_t)MM*DM];
__device__ float g_k   [(size_t)MM*DM];
__device__ float g_v   [(size_t)MM*DM];
__device__ float g_a   [(size_t)MM*DM];
__device__ float g_ar  [(size_t)MM*DM];
__device__ float g_beta [(size_t)MM*HH];
__device__ float g_gamma[(size_t)MM*HH];

__device__ __forceinline__ float sigmoidf_(float x) {
    return 1.0f / (1.0f + expf(-x));
}
__device__ __forceinline__ uint32_t smem_u32(const void* p) {
    return (uint32_t)__cvta_generic_to_shared(p);
}
__device__ __forceinline__ void cp16(uint32_t s, const void* g) {
    asm volatile("cp.async.cg.shared.global [%0], [%1], 16;" :: "r"(s), "l"(g));
}
#define CP_COMMIT() asm volatile("cp.async.commit_group;")
#define CP_WAIT(n)  asm volatile("cp.async.wait_group %0;" :: "n"(n))

#define LDSM_X4(r, addr) \
    asm volatile("ldmatrix.sync.aligned.m8n8.x4.shared.b16 {%0,%1,%2,%3}, [%4];" \
                 : "=r"((r)[0]), "=r"((r)[1]), "=r"((r)[2]), "=r"((r)[3]) : "r"(addr))

#define MMA16816(c, a, b0_, b1_) \
    asm volatile("mma.sync.aligned.m16n8k16.row.col.f32.f16.f16.f32 " \
                 "{%0,%1,%2,%3}, {%4,%5,%6,%7}, {%8,%9}, {%0,%1,%2,%3};" \
                 : "+f"((c)[0]), "+f"((c)[1]), "+f"((c)[2]), "+f"((c)[3]) \
                 : "r"((a)[0]), "r"((a)[1]), "r"((a)[2]), "r"((a)[3]), \
                   "r"(b0_), "r"(b1_))

#define GEMM_SMEM (65536 + 1024)

// ---------------- hi/lo fp16 split store (2 segments) ----------------
__device__ __forceinline__ void store_split(__half* dst, size_t base, int c,
                                            float4 v, bool a_layout) {
    __half h0 = __float2half_rn(v.x), h1 = __float2half_rn(v.y);
    __half h2 = __float2half_rn(v.z), h3 = __float2half_rn(v.w);
    __half2 hp0; hp0.x = h0; hp0.y = h1;
    __half2 hp1; hp1.x = h2; hp1.y = h3;
    __half2* p0 = (__half2*)(dst + base + c);
    __half2* p1 = (__half2*)(dst + base + 1024 + c);
    p0[0] = hp0; p0[1] = hp1;
    if (a_layout) {
        __half l0 = __float2half_rn(v.x - __half2float(h0));
        __half l1 = __float2half_rn(v.y - __half2float(h1));
        __half l2 = __float2half_rn(v.z - __half2float(h2));
        __half l3 = __float2half_rn(v.w - __half2float(h3));
        __half2 lp0; lp0.x = l0; lp0.y = l1;
        __half2 lp1; lp1.x = l2; lp1.y = l3;
        p1[0] = lp0; p1[1] = lp1;
    } else {
        p1[0] = hp0; p1[1] = hp1;
    }
}

// ---------------- LayerNorm -> A_cat (fp16 hi/lo) ----------------
__global__ void ln_kernel(const float* __restrict__ x,
                          const float* __restrict__ w,
                          const float* __restrict__ bsh) {
    __shared__ float sh[8];
    const int m = blockIdx.x;
    const int tid = threadIdx.x;
    const float* xr = x + (size_t)m * DM;

    float4 xv = *(const float4*)(xr + tid * 4);
    float s = xv.x + xv.y + xv.z + xv.w;
    #pragma unroll
    for (int o = 16; o; o >>= 1) s += __shfl_xor_sync(0xffffffffu, s, o);
    if ((tid & 31) == 0) sh[tid >> 5] = s;
    __syncthreads();
    float tot = 0.f;
    #pragma unroll
    for (int i = 0; i < 8; i++) tot += sh[i];
    const float mean = tot * (1.0f / 1024.0f);
    __syncthreads();

    float dx0 = xv.x - mean, dx1 = xv.y - mean, dx2 = xv.z - mean, dx3 = xv.w - mean;
    float s2 = dx0*dx0 + dx1*dx1 + dx2*dx2 + dx3*dx3;
    #pragma unroll
    for (int o = 16; o; o >>= 1) s2 += __shfl_xor_sync(0xffffffffu, s2, o);
    if ((tid & 31) == 0) sh[tid >> 5] = s2;
    __syncthreads();
    float tot2 = 0.f;
    #pragma unroll
    for (int i = 0; i < 8; i++) tot2 += sh[i];
    const float rstd = rsqrtf(tot2 * (1.0f / 1024.0f) + 1e-5f);

    float4 wv = *(const float4*)(w + tid * 4);
    float4 bv = *(const float4*)(bsh + tid * 4);
    float4 ov;
    ov.x = dx0 * rstd * wv.x + bv.x;
    ov.y = dx1 * rstd * wv.y + bv.y;
    ov.z = dx2 * rstd * wv.z + bv.z;
    ov.w = dx3 * rstd * wv.w + bv.w;

    store_split(g_acat, (size_t)m * K2, tid * 4, ov, true);
}

// ---------------- W_cat builder ----------------
__global__ void conv_w(const float* __restrict__ Wq, const float* __restrict__ Wk,
                       const float* __restrict__ Wv, const float* __restrict__ Wa,
                       const float* __restrict__ War, const float* __restrict__ Wb,
                       const float* __restrict__ Wg, const float* __restrict__ Wo) {
    const int n = blockIdx.x;
    const int c = threadIdx.x * 4;
    float4 v = {0.f, 0.f, 0.f, 0.f};
    const float* src = nullptr;
    if (n < 5120) {
        const int seg = n >> 10;
        const float* tab[5] = {Wq, Wk, Wv, Wa, War};
        src = tab[seg] + (size_t)(n & 1023) * DM;
    } else if (n < 5136) {
        src = Wb + (size_t)(n - 5120) * DM;
    } else if (n < 5152) {
        src = Wg + (size_t)(n - 5136) * DM;
    } else if (n >= 5376) {
        src = Wo + (size_t)(n - 5376) * DM;
    }
    if (src) v = *(const float4*)(src + c);
    store_split(g_wcat, (size_t)n * K2, c, v, false);
}

// ---------------- epilogue writer (2 consecutive cols) ----------------
__device__ __forceinline__ void epi_write2(int m, int n, float v0, float v1,
        const float* __restrict__ ba, const float* __restrict__ baR,
        const float* __restrict__ bb, const float* __restrict__ bgm,
        const float* __restrict__ xres, float* __restrict__ dout) {
    if (n < 3072) {
        float* outp = (n < 1024) ? g_q : (n < 2048 ? g_k : g_v);
        float2 w; w.x = v0; w.y = v1;
        *(float2*)(outp + (size_t)m * DM + (n & 1023)) = w;
    } else if (n < 5120) {
        float* outp = (n < 4096) ? g_a : g_ar;
        const float* bias = (n < 4096) ? ba : baR;
        const int col = n & 1023;
        float2 w;
        w.x = sigmoidf_(v0 + bias[col]);
        w.y = sigmoidf_(v1 + bias[col + 1]);
        *(float2*)(outp + (size_t)m * DM + col) = w;
    } else if (n < 5136) {
        const int j = n - 5120;
        g_beta[(size_t)m * HH + j]     = sigmoidf_(v0 + bb[j]);
        g_beta[(size_t)m * HH + j + 1] = sigmoidf_(v1 + bb[j + 1]);
    } else if (n < 5152) {
        const int j = n - 5136;
        g_gamma[(size_t)m * HH + j]     = sigmoidf_(v0 + bgm[j]);
        g_gamma[(size_t)m * HH + j + 1] = sigmoidf_(v1 + bgm[j + 1]);
    } else if (n < 5376) {
        // pad: drop
    } else {
        const int col = n - 5376;
        float2 r = *(const float2*)(xres + (size_t)m * DM + col);
        float2 w; w.x = v0 + r.x; w.y = v1 + r.y;
        *(float2*)(dout + (size_t)m * DM + col) = w;
    }
}

// ---- mma.sync fp16 GEMM: 128x128 CTA, 64x32 warp, 2-stage (R8 proven) ----
__global__ void __launch_bounds__(256, 2)
gemm_mma(const __half* __restrict__ A,
         const __half* __restrict__ Wc,
         int nbase,
         const float* __restrict__ ba, const float* __restrict__ baR,
         const float* __restrict__ bb, const float* __restrict__ bgm,
         const float* __restrict__ xres, float* __restrict__ dout) {
    extern __shared__ __align__(16) char dsm[];
    const int tid = threadIdx.x;
    const int wid = tid >> 5, lane = tid & 31;
    const int m0 = blockIdx.x * 128;
    const int n0g = nbase + blockIdx.y * 128;

    const uint32_t sbase = smem_u32(dsm);
    const uint32_t tile0 = (sbase + 1023) & ~1023u;
    const uint32_t sA = tile0;
    const uint32_t sW = tile0 + 32768;

    const __half* Aptr = A + (size_t)m0 * K2;
    const __half* Wptr = Wc + (size_t)n0g * K2;

    int cp_r[4], cp_soff[4];
    #pragma unroll
    for (int i = 0; i < 4; i++) {
        const int u = tid + i * 256;
        const int r = u >> 3, c16 = u & 7;
        cp_r[i] = r;
        cp_soff[i] = r * 128 + ((c16 ^ (r & 7)) * 16);
    }

#define ISSUE(cc_) do { \
    const int kc_ = (cc_) * 64; \
    const uint32_t ab_ = sA + ((cc_) & 1) * 16384; \
    const uint32_t wb_ = sW + ((cc_) & 1) * 16384; \
    _Pragma("unroll") \
    for (int i_ = 0; i_ < 4; i_++) { \
        const int c16_ = (tid + i_ * 256) & 7; \
        cp16(ab_ + cp_soff[i_], Aptr + (size_t)cp_r[i_] * K2 + kc_ + c16_ * 8); \
        cp16(wb_ + cp_soff[i_], Wptr + (size_t)cp_r[i_] * K2 + kc_ + c16_ * 8); \
    } \
    CP_COMMIT(); \
} while (0)

    float acc[4][4][4];
    #pragma unroll
    for (int i = 0; i < 4; i++)
        #pragma unroll
        for (int j = 0; j < 4; j++)
            #pragma unroll
            for (int e = 0; e < 4; e++) acc[i][j][e] = 0.f;

    const int mwarp = (wid >> 2) * 64;
    const int nwarp = (wid & 3) * 32;
    const int lrow  = lane & 15;
    const int lchunk = lane >> 4;

    ISSUE(0);
    ISSUE(1);

    for (int c = 0; c < NC; c++) {
        if (c + 1 < NC) { CP_WAIT(1); } else { CP_WAIT(0); }
        __syncthreads();

        const uint32_t ab = sA + (c & 1) * 16384;
        const uint32_t wb = sW + (c & 1) * 16384;

        #pragma unroll
        for (int ks = 0; ks < 4; ks++) {
            const int cc = ks * 2 + lchunk;
            uint32_t ar[4][4];
            #pragma unroll
            for (int fm = 0; fm < 4; fm++) {
                const int rr = mwarp + fm * 16 + lrow;
                LDSM_X4(ar[fm], ab + rr * 128 + ((cc ^ (rr & 7)) * 16));
            }
            uint32_t br[2][4];
            #pragma unroll
            for (int g = 0; g < 2; g++) {
                const int rr = nwarp + g * 16 + lrow;
                LDSM_X4(br[g], wb + rr * 128 + ((cc ^ (rr & 7)) * 16));
            }
            #pragma unroll
            for (int fm = 0; fm < 4; fm++)
                #pragma unroll
                for (int fn = 0; fn < 4; fn++)
                    MMA16816(acc[fm][fn], ar[fm],
                             br[fn >> 1][fn & 1], br[fn >> 1][2 + (fn & 1)]);
        }

        __syncthreads();
        if (c + 2 < NC) ISSUE(c + 2);
    }
#undef ISSUE

    // ---- epilogue ----
    const int mrow_lo = m0 + mwarp + (lane >> 2);
    const int ncol = n0g + nwarp + (lane & 3) * 2;
    #pragma unroll
    for (int fm = 0; fm < 4; fm++) {
        const int m_lo = mrow_lo + fm * 16;
        #pragma unroll
        for (int fn = 0; fn < 4; fn++) {
            const int n = ncol + fn * 8;
            epi_write2(m_lo,     n, acc[fm][fn][0], acc[fm][fn][1], ba, baR, bb, bgm, xres, dout);
            epi_write2(m_lo + 8, n, acc[fm][fn][2], acc[fm][fn][3], ba, baR, bb, bgm, xres, dout);
        }
    }
}

// ---------------- sequential scan: 128 blocks x 256 threads ----------------
// Single sync per step; staging of t+1 overlaps compute of t; 2-step prefetch.
// Staging groups (64 threads each): g0: K+Q (+norm), g1: V+beta/gamma, g2: A, g3: AR.

#define SCAN_STAGE(pp_, ff0_, ff1_) do { \
    if (g == 0) { \
        sk[pp_][idx] = (ff0_); sq[pp_][idx] = (ff1_); \
        float nn_ = (ff0_) * (ff0_); \
        _Pragma("unroll") \
        for (int o_ = 16; o_; o_ >>= 1) nn_ += __shfl_xor_sync(0xffffffffu, nn_, o_); \
        if ((tid & 31) == 0) snrm[pp_][tid >> 5] = nn_; \
    } else if (g == 1) { \
        sv[pp_][idx] = (ff0_); \
        if (idx < 2) sbg[pp_][idx] = (ff1_); \
    } else if (g == 2) { sa[pp_][idx] = (ff0_); } \
    else               { sr[pp_][idx] = (ff0_); } \
} while (0)

__global__ void __launch_bounds__(256, 1)
scan_kernel(const float* __restrict__ Q, const float* __restrict__ K,
            const float* __restrict__ V, const float* __restrict__ A,
            const float* __restrict__ AR,
            const float* __restrict__ Bt, const float* __restrict__ Gt,
            __half* __restrict__ Ocat) {
    const int bh = blockIdx.x >> 1;
    const int half_ = blockIdx.x & 1;
    const int b = bh >> 4, h = bh & 15;
    const int tid = threadIdx.x;
    const int c = tid >> 3;
    const int r8 = tid & 7;
    const int e = half_ * 32 + c;

    const size_t rb  = ((size_t)b * TT) * DM + (size_t)h * DH;
    size_t ob        = ((size_t)b * TT) * K2 + (size_t)h * DH + e;
    const size_t bgb = ((size_t)b * TT) * HH + h;

    __shared__ __align__(16) float sk[2][64], sq[2][64], sv[2][64], sa[2][64], sr[2][64];
    __shared__ float snrm[2][2], sbg[2][2];

    float S[8], R[8];
    #pragma unroll
    for (int i = 0; i < 8; i++) { S[i] = 0.f; R[i] = 0.f; }

    const int g = tid >> 6, idx = tid & 63;
    const float* p0 = nullptr; const float* p1 = nullptr;
    int s0 = DM, s1 = 0;
    if (g == 0)      { p0 = K + rb + idx; p1 = Q + rb + idx; s1 = DM; }
    else if (g == 1) { p0 = V + rb + idx;
                       if (idx == 0)      { p1 = Bt + bgb; s1 = HH; }
                       else if (idx == 1) { p1 = Gt + bgb; s1 = HH; } }
    else if (g == 2) { p0 = A + rb + idx; }
    else             { p0 = AR + rb + idx; }

    // prologue: stage step 0; prefetch step 1 -> (f0A,f1A), step 2 -> (f0B,f1B)
    float f0A = 0.f, f1A = 0.f, f0B = 0.f, f1B = 0.f;
    {
        float f0 = __ldg(p0);
        float f1 = (s1 ? __ldg(p1) : 0.f);
        SCAN_STAGE(0, f0, f1);
        p0 += s0; f0A = __ldg(p0);
        if (s1) { p1 += s1; f1A = __ldg(p1); }
        p0 += s0; f0B = __ldg(p0);
        if (s1) { p1 += s1; f1B = __ldg(p1); }
    }

    for (int t = 0; t < TT; t++) {
        const int p = t & 1;
        __syncthreads();   // smem[p] fully staged

        // ---- stage step t+1 into smem[p^1]; refill prefetch for t+3 ----
        if (t + 1 < TT) {
            if (t & 1) {
                SCAN_STAGE(p ^ 1, f0B, f1B);
                if (t + 3 < TT) {
                    p0 += s0; f0B = __ldg(p0);
                    if (s1) { p1 += s1; f1B = __ldg(p1); }
                }
            } else {
                SCAN_STAGE(p ^ 1, f0A, f1A);
                if (t + 3 < TT) {
                    p0 += s0; f0A = __ldg(p0);
                    if (s1) { p1 += s1; f1A = __ldg(p1); }
                }
            }
        }

        // ---- compute step t ----
        const float nrm2 = snrm[p][0] + snrm[p][1];
        const float invn = rsqrtf(fmaxf(nrm2, 1e-24f));

        float4 k0 = *(const float4*)&sk[p][r8 * 8];
        float4 k1 = *(const float4*)&sk[p][r8 * 8 + 4];
        float kn[8] = {k0.x*invn, k0.y*invn, k0.z*invn, k0.w*invn,
                       k1.x*invn, k1.y*invn, k1.z*invn, k1.w*invn};
        float4 q0 = *(const float4*)&sq[p][r8 * 8];
        float4 q1 = *(const float4*)&sq[p][r8 * 8 + 4];
        float qv[8] = {q0.x, q0.y, q0.z, q0.w, q1.x, q1.y, q1.z, q1.w};
        float4 a0 = *(const float4*)&sa[p][r8 * 8];
        float4 a1 = *(const float4*)&sa[p][r8 * 8 + 4];
        float av[8] = {a0.x, a0.y, a0.z, a0.w, a1.x, a1.y, a1.z, a1.w};
        float4 r0 = *(const float4*)&sr[p][r8 * 8];
        float4 r1 = *(const float4*)&sr[p][r8 * 8 + 4];
        float rv[8] = {r0.x, r0.y, r0.z, r0.w, r1.x, r1.y, r1.z, r1.w};

        const float beta  = sbg[p][0];
        const float gamma = sbg[p][1];
        const float ve = sv[p][e];

        // fused partials: pr (pre-decay S), kp (post-decay S), kr (post-decay R)
        float pr = 0.f, kp = 0.f, kr = 0.f;
        #pragma unroll
        for (int i = 0; i < 8; i++) {
            pr = fmaf(S[i], kn[i], pr);
            S[i] *= av[i];
            kp = fmaf(kn[i], S[i], kp);
            R[i] *= rv[i];
            kr = fmaf(kn[i], R[i], kr);
        }
        // three reductions, interleaved (independent shuffle chains)
        pr += __shfl_xor_sync(0xffffffffu, pr, 1);
        kp += __shfl_xor_sync(0xffffffffu, kp, 1);
        kr += __shfl_xor_sync(0xffffffffu, kr, 1);
        pr += __shfl_xor_sync(0xffffffffu, pr, 2);
        kp += __shfl_xor_sync(0xffffffffu, kp, 2);
        kr += __shfl_xor_sync(0xffffffffu, kr, 2);
        pr += __shfl_xor_sync(0xffffffffu, pr, 4);
        kp += __shfl_xor_sync(0xffffffffu, kp, 4);
        kr += __shfl_xor_sync(0xffffffffu, kr, 4);

        const float re = fminf(fmaxf(ve - pr, -1.0f), 1.0f);
        const float cf = beta * (ve - kp);
        const float cr = gamma * (re - kr);

        // updates + output partials (even/odd accumulators for ILP)
        float osa = 0.f, osb = 0.f;
        #pragma unroll
        for (int i = 0; i < 8; i += 2) {
            S[i]   = fmaf(kn[i],   cf, S[i]);   osa = fmaf(S[i],   qv[i],   osa);
            S[i+1] = fmaf(kn[i+1], cf, S[i+1]); osb = fmaf(S[i+1], qv[i+1], osb);
        }
        #pragma unroll
        for (int i = 0; i < 8; i += 2) {
            R[i]   = fmaf(kn[i],   cr, R[i]);   osa = fmaf(R[i],   qv[i],   osa);
            R[i+1] = fmaf(kn[i+1], cr, R[i+1]); osb = fmaf(R[i+1], qv[i+1], osb);
        }
        float os = osa + osb;
        os += __shfl_xor_sync(0xffffffffu, os, 1);
        os += __shfl_xor_sync(0xffffffffu, os, 2);
        os += __shfl_xor_sync(0xffffffffu, os, 4);

        if (r8 == 0) {
            __half hv = __float2half_rn(os);
            __half lv = __float2half_rn(os - __half2float(hv));
            Ocat[ob]        = hv;
            Ocat[ob + 1024] = lv;
        }
        ob += K2;
    }
}

// ---------------- launch ----------------
extern "C" void kernel_launch(void* const* d_in, const int* in_sizes, int n_in,
                              void* d_out, int out_size) {
    const float* x    = (const float*)d_in[0];
    const float* Wq   = (const float*)d_in[1];
    const float* Wk   = (const float*)d_in[2];
    const float* Wv   = (const float*)d_in[3];
    const float* Wa   = (const float*)d_in[4];
    const float* ba   = (const float*)d_in[5];
    const float* Wb   = (const float*)d_in[6];
    const float* bb   = (const float*)d_in[7];
    const float* Wg   = (const float*)d_in[8];
    const float* bgm  = (const float*)d_in[9];
    const float* War  = (const float*)d_in[10];
    const float* baR  = (const float*)d_in[11];
    const float* Wo   = (const float*)d_in[12];
    const float* ln_w = (const float*)d_in[13];
    const float* ln_b = (const float*)d_in[14];
    float* out = (float*)d_out;

    __half *acat, *ocat, *wcat;
    float *q, *k, *v, *a, *ar, *bet, *gam;
    cudaGetSymbolAddress((void**)&acat, g_acat);
    cudaGetSymbolAddress((void**)&ocat, g_ocat);
    cudaGetSymbolAddress((void**)&wcat, g_wcat);
    cudaGetSymbolAddress((void**)&q,   g_q);
    cudaGetSymbolAddress((void**)&k,   g_k);
    cudaGetSymbolAddress((void**)&v,   g_v);
    cudaGetSymbolAddress((void**)&a,   g_a);
    cudaGetSymbolAddress((void**)&ar,  g_ar);
    cudaGetSymbolAddress((void**)&bet, g_beta);
    cudaGetSymbolAddress((void**)&gam, g_gamma);

    static int smem_set = 0;
    if (!smem_set) {
        cudaFuncSetAttribute(gemm_mma, cudaFuncAttributeMaxDynamicSharedMemorySize, GEMM_SMEM);
        smem_set = 1;
    }

    ln_kernel<<<MM, 256>>>(x, ln_w, ln_b);
    conv_w<<<NWC, 256>>>(Wq, Wk, Wv, Wa, War, Wb, Wg, Wo);
    // proj + head gates: n in [0, 5376)
    gemm_mma<<<dim3(MM/128, 42), 256, GEMM_SMEM>>>(acat, wcat, 0, ba, baR, bb, bgm,
                                                   nullptr, nullptr);
    scan_kernel<<<128, 256>>>(q, k, v, a, ar, bet, gam, ocat);
    // output proj: n in [5376, 6400)
    gemm_mma<<<dim3(MM/128, 8), 256, GEMM_SMEM>>>(ocat, wcat, 5376, ba, baR, bb, bgm,
                                                  x, out);
}

// round 13
// speedup vs baseline: 1.6470x; 1.1777x over previous
#include <cuda_runtime.h>
#include <cuda_fp16.h>
#include <math.h>
#include <stdint.h>

// Problem constants
#define BB 4
#define TT 2048
#define DM 1024
#define HH 16
#define DH 64
#define MM (BB*TT)          // 8192 rows
#define K2 2048             // split-K: [Ah | Al] (A)  x  [Wh | Wh] (W)  => A . fp16(W)
#define NWC 6400            // W_cat rows: 5*1024 proj + 16 b + 16 g + 224 pad + 1024 Wo
#define NC 32               // K2 / 64

// ---------------- scratch ----------------
__device__ __half g_acat[(size_t)MM*K2];
__device__ __half g_ocat[(size_t)MM*K2];
__device__ __half g_wcat[(size_t)NWC*K2];
__device__ float g_q   [(size_t)MM*DM];
__device__ float g_k   [(size_t)MM*DM];
__device__ float g_v   [(size_t)MM*DM];
__device__ float g_a   [(size_t)MM*DM];
__device__ float g_ar  [(size_t)MM*DM];
__device__ float g_beta [(size_t)MM*HH];
__device__ float g_gamma[(size_t)MM*HH];

__device__ __forceinline__ float sigmoidf_(float x) {
    return 1.0f / (1.0f + expf(-x));
}
__device__ __forceinline__ uint32_t smem_u32(const void* p) {
    return (uint32_t)__cvta_generic_to_shared(p);
}
__device__ __forceinline__ void cp16(uint32_t s, const void* g) {
    asm volatile("cp.async.cg.shared.global [%0], [%1], 16;" :: "r"(s), "l"(g));
}
__device__ __forceinline__ void cp4(uint32_t s, const void* g) {
    asm volatile("cp.async.ca.shared.global [%0], [%1], 4;" :: "r"(s), "l"(g));
}
#define CP_COMMIT() asm volatile("cp.async.commit_group;")
#define CP_WAIT(n)  asm volatile("cp.async.wait_group %0;" :: "n"(n))

#define LDSM_X4(r, addr) \
    asm volatile("ldmatrix.sync.aligned.m8n8.x4.shared.b16 {%0,%1,%2,%3}, [%4];" \
                 : "=r"((r)[0]), "=r"((r)[1]), "=r"((r)[2]), "=r"((r)[3]) : "r"(addr))

#define MMA16816(c, a, b0_, b1_) \
    asm volatile("mma.sync.aligned.m16n8k16.row.col.f32.f16.f16.f32 " \
                 "{%0,%1,%2,%3}, {%4,%5,%6,%7}, {%8,%9}, {%0,%1,%2,%3};" \
                 : "+f"((c)[0]), "+f"((c)[1]), "+f"((c)[2]), "+f"((c)[3]) \
                 : "r"((a)[0]), "r"((a)[1]), "r"((a)[2]), "r"((a)[3]), \
                   "r"(b0_), "r"(b1_))

#define GEMM_SMEM (65536 + 1024)

// ---------------- hi/lo fp16 split store (2 segments) ----------------
__device__ __forceinline__ void store_split(__half* dst, size_t base, int c,
                                            float4 v, bool a_layout) {
    __half h0 = __float2half_rn(v.x), h1 = __float2half_rn(v.y);
    __half h2 = __float2half_rn(v.z), h3 = __float2half_rn(v.w);
    __half2 hp0; hp0.x = h0; hp0.y = h1;
    __half2 hp1; hp1.x = h2; hp1.y = h3;
    __half2* p0 = (__half2*)(dst + base + c);
    __half2* p1 = (__half2*)(dst + base + 1024 + c);
    p0[0] = hp0; p0[1] = hp1;
    if (a_layout) {
        __half l0 = __float2half_rn(v.x - __half2float(h0));
        __half l1 = __float2half_rn(v.y - __half2float(h1));
        __half l2 = __float2half_rn(v.z - __half2float(h2));
        __half l3 = __float2half_rn(v.w - __half2float(h3));
        __half2 lp0; lp0.x = l0; lp0.y = l1;
        __half2 lp1; lp1.x = l2; lp1.y = l3;
        p1[0] = lp0; p1[1] = lp1;
    } else {
        p1[0] = hp0; p1[1] = hp1;
    }
}

// ---------------- LayerNorm -> A_cat (fp16 hi/lo) ----------------
__global__ void ln_kernel(const float* __restrict__ x,
                          const float* __restrict__ w,
                          const float* __restrict__ bsh) {
    __shared__ float sh[8];
    const int m = blockIdx.x;
    const int tid = threadIdx.x;
    const float* xr = x + (size_t)m * DM;

    float4 xv = *(const float4*)(xr + tid * 4);
    float s = xv.x + xv.y + xv.z + xv.w;
    #pragma unroll
    for (int o = 16; o; o >>= 1) s += __shfl_xor_sync(0xffffffffu, s, o);
    if ((tid & 31) == 0) sh[tid >> 5] = s;
    __syncthreads();
    float tot = 0.f;
    #pragma unroll
    for (int i = 0; i < 8; i++) tot += sh[i];
    const float mean = tot * (1.0f / 1024.0f);
    __syncthreads();

    float dx0 = xv.x - mean, dx1 = xv.y - mean, dx2 = xv.z - mean, dx3 = xv.w - mean;
    float s2 = dx0*dx0 + dx1*dx1 + dx2*dx2 + dx3*dx3;
    #pragma unroll
    for (int o = 16; o; o >>= 1) s2 += __shfl_xor_sync(0xffffffffu, s2, o);
    if ((tid & 31) == 0) sh[tid >> 5] = s2;
    __syncthreads();
    float tot2 = 0.f;
    #pragma unroll
    for (int i = 0; i < 8; i++) tot2 += sh[i];
    const float rstd = rsqrtf(tot2 * (1.0f / 1024.0f) + 1e-5f);

    float4 wv = *(const float4*)(w + tid * 4);
    float4 bv = *(const float4*)(bsh + tid * 4);
    float4 ov;
    ov.x = dx0 * rstd * wv.x + bv.x;
    ov.y = dx1 * rstd * wv.y + bv.y;
    ov.z = dx2 * rstd * wv.z + bv.z;
    ov.w = dx3 * rstd * wv.w + bv.w;

    store_split(g_acat, (size_t)m * K2, tid * 4, ov, true);
}

// ---------------- W_cat builder ----------------
__global__ void conv_w(const float* __restrict__ Wq, const float* __restrict__ Wk,
                       const float* __restrict__ Wv, const float* __restrict__ Wa,
                       const float* __restrict__ War, const float* __restrict__ Wb,
                       const float* __restrict__ Wg, const float* __restrict__ Wo) {
    const int n = blockIdx.x;
    const int c = threadIdx.x * 4;
    float4 v = {0.f, 0.f, 0.f, 0.f};
    const float* src = nullptr;
    if (n < 5120) {
        const int seg = n >> 10;
        const float* tab[5] = {Wq, Wk, Wv, Wa, War};
        src = tab[seg] + (size_t)(n & 1023) * DM;
    } else if (n < 5136) {
        src = Wb + (size_t)(n - 5120) * DM;
    } else if (n < 5152) {
        src = Wg + (size_t)(n - 5136) * DM;
    } else if (n >= 5376) {
        src = Wo + (size_t)(n - 5376) * DM;
    }
    if (src) v = *(const float4*)(src + c);
    store_split(g_wcat, (size_t)n * K2, c, v, false);
}

// ---------------- epilogue writer (2 consecutive cols) ----------------
__device__ __forceinline__ void epi_write2(int m, int n, float v0, float v1,
        const float* __restrict__ ba, const float* __restrict__ baR,
        const float* __restrict__ bb, const float* __restrict__ bgm,
        const float* __restrict__ xres, float* __restrict__ dout) {
    if (n < 3072) {
        float* outp = (n < 1024) ? g_q : (n < 2048 ? g_k : g_v);
        float2 w; w.x = v0; w.y = v1;
        *(float2*)(outp + (size_t)m * DM + (n & 1023)) = w;
    } else if (n < 5120) {
        float* outp = (n < 4096) ? g_a : g_ar;
        const float* bias = (n < 4096) ? ba : baR;
        const int col = n & 1023;
        float2 w;
        w.x = sigmoidf_(v0 + bias[col]);
        w.y = sigmoidf_(v1 + bias[col + 1]);
        *(float2*)(outp + (size_t)m * DM + col) = w;
    } else if (n < 5136) {
        const int j = n - 5120;
        g_beta[(size_t)m * HH + j]     = sigmoidf_(v0 + bb[j]);
        g_beta[(size_t)m * HH + j + 1] = sigmoidf_(v1 + bb[j + 1]);
    } else if (n < 5152) {
        const int j = n - 5136;
        g_gamma[(size_t)m * HH + j]     = sigmoidf_(v0 + bgm[j]);
        g_gamma[(size_t)m * HH + j + 1] = sigmoidf_(v1 + bgm[j + 1]);
    } else if (n < 5376) {
        // pad: drop
    } else {
        const int col = n - 5376;
        float2 r = *(const float2*)(xres + (size_t)m * DM + col);
        float2 w; w.x = v0 + r.x; w.y = v1 + r.y;
        *(float2*)(dout + (size_t)m * DM + col) = w;
    }
}

// ---- mma.sync fp16 GEMM: 128x128 CTA, 64x32 warp, 2-stage (R8 proven) ----
__global__ void __launch_bounds__(256, 2)
gemm_mma(const __half* __restrict__ A,
         const __half* __restrict__ Wc,
         int nbase,
         const float* __restrict__ ba, const float* __restrict__ baR,
         const float* __restrict__ bb, const float* __restrict__ bgm,
         const float* __restrict__ xres, float* __restrict__ dout) {
    extern __shared__ __align__(16) char dsm[];
    const int tid = threadIdx.x;
    const int wid = tid >> 5, lane = tid & 31;
    const int m0 = blockIdx.x * 128;
    const int n0g = nbase + blockIdx.y * 128;

    const uint32_t sbase = smem_u32(dsm);
    const uint32_t tile0 = (sbase + 1023) & ~1023u;
    const uint32_t sA = tile0;
    const uint32_t sW = tile0 + 32768;

    const __half* Aptr = A + (size_t)m0 * K2;
    const __half* Wptr = Wc + (size_t)n0g * K2;

    int cp_r[4], cp_soff[4];
    #pragma unroll
    for (int i = 0; i < 4; i++) {
        const int u = tid + i * 256;
        const int r = u >> 3, c16 = u & 7;
        cp_r[i] = r;
        cp_soff[i] = r * 128 + ((c16 ^ (r & 7)) * 16);
    }

#define ISSUE(cc_) do { \
    const int kc_ = (cc_) * 64; \
    const uint32_t ab_ = sA + ((cc_) & 1) * 16384; \
    const uint32_t wb_ = sW + ((cc_) & 1) * 16384; \
    _Pragma("unroll") \
    for (int i_ = 0; i_ < 4; i_++) { \
        const int c16_ = (tid + i_ * 256) & 7; \
        cp16(ab_ + cp_soff[i_], Aptr + (size_t)cp_r[i_] * K2 + kc_ + c16_ * 8); \
        cp16(wb_ + cp_soff[i_], Wptr + (size_t)cp_r[i_] * K2 + kc_ + c16_ * 8); \
    } \
    CP_COMMIT(); \
} while (0)

    float acc[4][4][4];
    #pragma unroll
    for (int i = 0; i < 4; i++)
        #pragma unroll
        for (int j = 0; j < 4; j++)
            #pragma unroll
            for (int e = 0; e < 4; e++) acc[i][j][e] = 0.f;

    const int mwarp = (wid >> 2) * 64;
    const int nwarp = (wid & 3) * 32;
    const int lrow  = lane & 15;
    const int lchunk = lane >> 4;

    ISSUE(0);
    ISSUE(1);

    for (int c = 0; c < NC; c++) {
        if (c + 1 < NC) { CP_WAIT(1); } else { CP_WAIT(0); }
        __syncthreads();

        const uint32_t ab = sA + (c & 1) * 16384;
        const uint32_t wb = sW + (c & 1) * 16384;

        #pragma unroll
        for (int ks = 0; ks < 4; ks++) {
            const int cc = ks * 2 + lchunk;
            uint32_t ar[4][4];
            #pragma unroll
            for (int fm = 0; fm < 4; fm++) {
                const int rr = mwarp + fm * 16 + lrow;
                LDSM_X4(ar[fm], ab + rr * 128 + ((cc ^ (rr & 7)) * 16));
            }
            uint32_t br[2][4];
            #pragma unroll
            for (int g = 0; g < 2; g++) {
                const int rr = nwarp + g * 16 + lrow;
                LDSM_X4(br[g], wb + rr * 128 + ((cc ^ (rr & 7)) * 16));
            }
            #pragma unroll
            for (int fm = 0; fm < 4; fm++)
                #pragma unroll
                for (int fn = 0; fn < 4; fn++)
                    MMA16816(acc[fm][fn], ar[fm],
                             br[fn >> 1][fn & 1], br[fn >> 1][2 + (fn & 1)]);
        }

        __syncthreads();
        if (c + 2 < NC) ISSUE(c + 2);
    }
#undef ISSUE

    // ---- epilogue ----
    const int mrow_lo = m0 + mwarp + (lane >> 2);
    const int ncol = n0g + nwarp + (lane & 3) * 2;
    #pragma unroll
    for (int fm = 0; fm < 4; fm++) {
        const int m_lo = mrow_lo + fm * 16;
        #pragma unroll
        for (int fn = 0; fn < 4; fn++) {
            const int n = ncol + fn * 8;
            epi_write2(m_lo,     n, acc[fm][fn][0], acc[fm][fn][1], ba, baR, bb, bgm, xres, dout);
            epi_write2(m_lo + 8, n, acc[fm][fn][2], acc[fm][fn][3], ba, baR, bb, bgm, xres, dout);
        }
    }
}

// ---------------- sequential scan: 256 blocks x 128 threads ----------------
// One block per (b, h, quarter): 16 columns, 8 threads/column.
// cp.async staging, 4 buffers, wait_group(2), ONE barrier per step.
// Raw-k reductions: ss/pr/kp/kr in one fused loop -> one 3-shuffle wave.

#define SC_BUF 288   // floats per buffer: k64 q64 a64 ar64 v16 bg2 pad

__global__ void __launch_bounds__(128, 2)
scan_kernel(const float* __restrict__ Q, const float* __restrict__ K,
            const float* __restrict__ V, const float* __restrict__ A,
            const float* __restrict__ AR,
            const float* __restrict__ Bt, const float* __restrict__ Gt,
            __half* __restrict__ Ocat) {
    const int bhq = blockIdx.x;              // 0..255
    const int quarter = bhq & 3;
    const int h = (bhq >> 2) & 15;
    const int b = bhq >> 6;
    const int tid = threadIdx.x;
    const int cl = tid >> 3;                 // local column 0..15
    const int r8 = tid & 7;                  // row octet
    const int e  = quarter * 16 + cl;        // column within head

    const size_t rb  = ((size_t)b * TT) * DM + (size_t)h * DH;   // + t*DM
    size_t ob        = ((size_t)b * TT) * K2 + (size_t)h * DH + e;
    const size_t bgb = ((size_t)b * TT) * HH + h;                // + t*HH

    __shared__ __align__(16) float sbuf[4][SC_BUF];
    const uint32_t sb0 = smem_u32(&sbuf[0][0]);

    float S[8], R[8];
    #pragma unroll
    for (int i = 0; i < 8; i++) { S[i] = 0.f; R[i] = 0.f; }

    // staging role
    const int role = tid >> 4;               // 0..7 groups of 16
    const int ridx = tid & 15;

#define SC_ISSUE(tt_) do { \
    const uint32_t dbuf_ = sb0 + ((tt_) & 3) * (SC_BUF * 4); \
    if (role == 0)      cp16(dbuf_ + ridx * 16,        K  + rb + (size_t)(tt_) * DM + ridx * 4); \
    else if (role == 1) cp16(dbuf_ + 256 + ridx * 16,  Q  + rb + (size_t)(tt_) * DM + ridx * 4); \
    else if (role == 2) cp16(dbuf_ + 512 + ridx * 16,  A  + rb + (size_t)(tt_) * DM + ridx * 4); \
    else if (role == 3) cp16(dbuf_ + 768 + ridx * 16,  AR + rb + (size_t)(tt_) * DM + ridx * 4); \
    else if (role == 4) cp4(dbuf_ + 1024 + ridx * 4,   V  + rb + (size_t)(tt_) * DM + quarter * 16 + ridx); \
    else if (role == 5 && ridx == 0) cp4(dbuf_ + 1088, Bt + bgb + (size_t)(tt_) * HH); \
    else if (role == 5 && ridx == 1) cp4(dbuf_ + 1092, Gt + bgb + (size_t)(tt_) * HH); \
    CP_COMMIT(); \
} while (0)

    SC_ISSUE(0); SC_ISSUE(1); SC_ISSUE(2);

    for (int t = 0; t < TT; t++) {
        CP_WAIT(2);
        __syncthreads();          // buffer t&3 staged for all threads

        if (t + 3 < TT) SC_ISSUE(t + 3);   // into buffer freed at step t-1

        const float* bf = sbuf[t & 3];

        // loads (conflict-free: broadcast across column pairs)
        float4 k0 = *(const float4*)&bf[r8 * 8];
        float4 k1 = *(const float4*)&bf[r8 * 8 + 4];
        float kv[8] = {k0.x, k0.y, k0.z, k0.w, k1.x, k1.y, k1.z, k1.w};
        float4 q0 = *(const float4*)&bf[64 + r8 * 8];
        float4 q1 = *(const float4*)&bf[64 + r8 * 8 + 4];
        float qv[8] = {q0.x, q0.y, q0.z, q0.w, q1.x, q1.y, q1.z, q1.w};
        float4 a0 = *(const float4*)&bf[128 + r8 * 8];
        float4 a1 = *(const float4*)&bf[128 + r8 * 8 + 4];
        float av[8] = {a0.x, a0.y, a0.z, a0.w, a1.x, a1.y, a1.z, a1.w};
        float4 w0 = *(const float4*)&bf[192 + r8 * 8];
        float4 w1 = *(const float4*)&bf[192 + r8 * 8 + 4];
        float rv[8] = {w0.x, w0.y, w0.z, w0.w, w1.x, w1.y, w1.z, w1.w};
        const float ve   = bf[256 + cl];
        const float beta = bf[272];
        const float gamma= bf[273];

        // fused partials on RAW k: ss, pr (pre-decay S), kp (post), kr (post)
        float ss = 0.f, pr = 0.f, kp = 0.f, kr = 0.f;
        #pragma unroll
        for (int i = 0; i < 8; i++) {
            ss = fmaf(kv[i], kv[i], ss);
            pr = fmaf(S[i], kv[i], pr);
            S[i] *= av[i];
            kp = fmaf(kv[i], S[i], kp);
            R[i] *= rv[i];
            kr = fmaf(kv[i], R[i], kr);
        }
        // one reduction wave: 4 parallel chains x 3 shuffles (within r8 group)
        ss += __shfl_xor_sync(0xffffffffu, ss, 1);
        pr += __shfl_xor_sync(0xffffffffu, pr, 1);
        kp += __shfl_xor_sync(0xffffffffu, kp, 1);
        kr += __shfl_xor_sync(0xffffffffu, kr, 1);
        ss += __shfl_xor_sync(0xffffffffu, ss, 2);
        pr += __shfl_xor_sync(0xffffffffu, pr, 2);
        kp += __shfl_xor_sync(0xffffffffu, kp, 2);
        kr += __shfl_xor_sync(0xffffffffu, kr, 2);
        ss += __shfl_xor_sync(0xffffffffu, ss, 4);
        pr += __shfl_xor_sync(0xffffffffu, pr, 4);
        kp += __shfl_xor_sync(0xffffffffu, kp, 4);
        kr += __shfl_xor_sync(0xffffffffu, kr, 4);

        const float invn = rsqrtf(fmaxf(ss, 1e-24f));
        const float re = fminf(fmaxf(ve - pr * invn, -1.0f), 1.0f);
        const float cfs = beta  * (ve - kp * invn) * invn;
        const float crs = gamma * (re - kr * invn) * invn;

        // rank-1 updates + output partials (recurrence path ends at S/R update)
        float osa = 0.f, osb = 0.f;
        #pragma unroll
        for (int i = 0; i < 8; i += 2) {
            S[i]   = fmaf(kv[i],   cfs, S[i]);   osa = fmaf(S[i],   qv[i],   osa);
            S[i+1] = fmaf(kv[i+1], cfs, S[i+1]); osb = fmaf(S[i+1], qv[i+1], osb);
            R[i]   = fmaf(kv[i],   crs, R[i]);   osa = fmaf(R[i],   qv[i],   osa);
            R[i+1] = fmaf(kv[i+1], crs, R[i+1]); osb = fmaf(R[i+1], qv[i+1], osb);
        }
        float os = osa + osb;
        os += __shfl_xor_sync(0xffffffffu, os, 1);
        os += __shfl_xor_sync(0xffffffffu, os, 2);
        os += __shfl_xor_sync(0xffffffffu, os, 4);

        if (r8 == 0) {
            __half hv = __float2half_rn(os);
            __half lv = __float2half_rn(os - __half2float(hv));
            Ocat[ob]        = hv;
            Ocat[ob + 1024] = lv;
        }
        ob += K2;
    }
#undef SC_ISSUE
}

// ---------------- launch ----------------
extern "C" void kernel_launch(void* const* d_in, const int* in_sizes, int n_in,
                              void* d_out, int out_size) {
    const float* x    = (const float*)d_in[0];
    const float* Wq   = (const float*)d_in[1];
    const float* Wk   = (const float*)d_in[2];
    const float* Wv   = (const float*)d_in[3];
    const float* Wa   = (const float*)d_in[4];
    const float* ba   = (const float*)d_in[5];
    const float* Wb   = (const float*)d_in[6];
    const float* bb   = (const float*)d_in[7];
    const float* Wg   = (const float*)d_in[8];
    const float* bgm  = (const float*)d_in[9];
    const float* War  = (const float*)d_in[10];
    const float* baR  = (const float*)d_in[11];
    const float* Wo   = (const float*)d_in[12];
    const float* ln_w = (const float*)d_in[13];
    const float* ln_b = (const float*)d_in[14];
    float* out = (float*)d_out;

    __half *acat, *ocat, *wcat;
    float *q, *k, *v, *a, *ar, *bet, *gam;
    cudaGetSymbolAddress((void**)&acat, g_acat);
    cudaGetSymbolAddress((void**)&ocat, g_ocat);
    cudaGetSymbolAddress((void**)&wcat, g_wcat);
    cudaGetSymbolAddress((void**)&q,   g_q);
    cudaGetSymbolAddress((void**)&k,   g_k);
    cudaGetSymbolAddress((void**)&v,   g_v);
    cudaGetSymbolAddress((void**)&a,   g_a);
    cudaGetSymbolAddress((void**)&ar,  g_ar);
    cudaGetSymbolAddress((void**)&bet, g_beta);
    cudaGetSymbolAddress((void**)&gam, g_gamma);

    static int smem_set = 0;
    if (!smem_set) {
        cudaFuncSetAttribute(gemm_mma, cudaFuncAttributeMaxDynamicSharedMemorySize, GEMM_SMEM);
        smem_set = 1;
    }

    ln_kernel<<<MM, 256>>>(x, ln_w, ln_b);
    conv_w<<<NWC, 256>>>(Wq, Wk, Wv, Wa, War, Wb, Wg, Wo);
    // proj + head gates: n in [0, 5376)
    gemm_mma<<<dim3(MM/128, 42), 256, GEMM_SMEM>>>(acat, wcat, 0, ba, baR, bb, bgm,
                                                   nullptr, nullptr);
    scan_kernel<<<256, 128>>>(q, k, v, a, ar, bet, gam, ocat);
    // output proj: n in [5376, 6400)
    gemm_mma<<<dim3(MM/128, 8), 256, GEMM_SMEM>>>(ocat, wcat, 5376, ba, baR, bb, bgm,
                                                  x, out);
}